// round 7
// baseline (speedup 1.0000x reference)
#include <cuda_runtime.h>

#define NB 4
#define LL 8192
#define SSZ 8192
#define HH 8
#define DD 64
#define NH (NB * HH)
#define CH 32            // s-chunks per (n,h); 256 s per chunk
#define PART_STRIDE 4160 // 4096 kv + 64 ksum
#define EPS 1e-6f
#define QPAD 68

typedef unsigned long long u64;

__device__ float g_part[NH * CH * PART_STRIDE];
__device__ float g_kv[NH * DD * DD];
__device__ float g_ksum[NH * DD];

__device__ __forceinline__ float fmap(float x) {
    return x > 0.f ? x + 1.f : __expf(x);
}

__device__ __forceinline__ u64 splat2(float a) {
    u64 r;
    asm("mov.b64 %0, {%1, %1};" : "=l"(r) : "f"(a));
    return r;
}

__device__ __forceinline__ u64 pack2(float lo, float hi) {
    u64 r;
    asm("mov.b64 %0, {%1, %2};" : "=l"(r) : "f"(lo), "f"(hi));
    return r;
}

__device__ __forceinline__ u64 ffma2(u64 a, u64 b, u64 c) {
    u64 d;
    asm("fma.rn.f32x2 %0, %1, %2, %3;" : "=l"(d) : "l"(a), "l"(b), "l"(c));
    return d;
}

// Kernel A: partial kv over a 256-s chunk.
// 128 threads (tx=t&15 v-group, ty=t>>4 d-group), 8d x 4v fragment (32 acc regs).
// kf staged as duplicated (f,f) u64 pairs -> a-operand is FFMA2-ready, no splat MOVs.
__global__ __launch_bounds__(128, 5) void kv_partial_kernel(
    const float* __restrict__ kin, const float* __restrict__ vin,
    const float* __restrict__ kv_mask)
{
    __shared__ u64  ksd[32][64];      // 16 KB: dup pairs of featurized k
    __shared__ float vs[32][64];      // 8 KB
    __shared__ float ksum_sc[8][64];  // 2 KB

    const int nh = blockIdx.x;
    const int n = nh >> 3, h = nh & 7;
    const int s0 = blockIdx.y * 256;
    const int t = threadIdx.x;
    const int tx = t & 15, ty = t >> 4;

    u64 acc2[8][2] = {};
    float4 ksum4 = make_float4(0.f, 0.f, 0.f, 0.f);

    #pragma unroll 1
    for (int tile = 0; tile < 8; tile++) {
        // stage 32x64 tile: ks duplicated pairs + vs, accumulate ksum from regs
        #pragma unroll
        for (int e = 0; e < 4; e++) {
            int idx = t + e * 128;
            int r = idx >> 4, c4 = (idx & 15) * 4;   // c4 == tx*4 (128 % 16 == 0)
            int s = s0 + tile * 32 + r;
            float m = kv_mask[n * SSZ + s];
            size_t g = (((size_t)(n * SSZ + s)) * HH + h) * DD + c4;
            float4 kq = *(const float4*)&kin[g];
            float4 vq = *(const float4*)&vin[g];
            float f0 = fmap(kq.x) * m, f1 = fmap(kq.y) * m;
            float f2 = fmap(kq.z) * m, f3 = fmap(kq.w) * m;
            ksum4.x += f0; ksum4.y += f1; ksum4.z += f2; ksum4.w += f3;
            ulonglong2 p01, p23;
            p01.x = splat2(f0); p01.y = splat2(f1);
            p23.x = splat2(f2); p23.y = splat2(f3);
            *(ulonglong2*)&ksd[r][c4]     = p01;
            *(ulonglong2*)&ksd[r][c4 + 2] = p23;
            *(float4*)&vs[r][c4] = make_float4(vq.x * m, vq.y * m,
                                               vq.z * m, vq.w * m);
        }
        __syncthreads();

        #pragma unroll 4
        for (int s = 0; s < 32; s++) {
            float4 vv = *(const float4*)&vs[s][tx * 4];
            u64 b0 = ((const u64*)&vv)[0];
            u64 b1 = ((const u64*)&vv)[1];
            ulonglong2 a01 = *(const ulonglong2*)&ksd[s][ty * 4];
            ulonglong2 a23 = *(const ulonglong2*)&ksd[s][ty * 4 + 2];
            ulonglong2 a45 = *(const ulonglong2*)&ksd[s][32 + ty * 4];
            ulonglong2 a67 = *(const ulonglong2*)&ksd[s][32 + ty * 4 + 2];
            u64 a[8] = {a01.x, a01.y, a23.x, a23.y, a45.x, a45.y, a67.x, a67.y};
            #pragma unroll
            for (int i = 0; i < 8; i++) {
                acc2[i][0] = ffma2(a[i], b0, acc2[i][0]);
                acc2[i][1] = ffma2(a[i], b1, acc2[i][1]);
            }
        }
        __syncthreads();
    }

    // ksum reduce: thread (ty,tx) owns cols tx*4..+3 for staged rows; 8 ty-groups to sum
    *(float4*)&ksum_sc[ty][tx * 4] = ksum4;
    __syncthreads();

    float* part = &g_part[(nh * CH + blockIdx.y) * PART_STRIDE];

    #pragma unroll
    for (int i = 0; i < 8; i++) {
        int row = (i < 4) ? (ty * 4 + i) : (32 + ty * 4 + i - 4);
        float4 f;
        ((u64*)&f)[0] = acc2[i][0];
        ((u64*)&f)[1] = acc2[i][1];
        *(float4*)&part[row * 64 + tx * 4] = f;
    }
    if (t < 64) {
        float s = 0.f;
        #pragma unroll
        for (int g = 0; g < 8; g++) s += ksum_sc[g][t];
        part[4096 + t] = s;
    }
}

// Reduce 32 partials -> final kv + ksum. 520*256 == 32*4160 exactly.
__global__ __launch_bounds__(256) void kv_reduce_kernel() {
    int idx = blockIdx.x * 256 + threadIdx.x;
    int nh = idx / PART_STRIDE;
    int el = idx - nh * PART_STRIDE;
    float s = 0.f;
    #pragma unroll 8
    for (int ch = 0; ch < CH; ch++)
        s += g_part[(nh * CH + ch) * PART_STRIDE + el];
    if (el < 4096) g_kv[nh * 4096 + el] = s;
    else           g_ksum[nh * 64 + el - 4096] = s;
}

// Kernel B: out = (qf . kv) / (qf . ksum + eps). 128 threads, 128 l-rows/CTA.
#define OUT_SMEM_BYTES (128 * QPAD * 4 + 64 * 64 * 4 + 64 * 4 + 128 * 4)

__global__ __launch_bounds__(128, 4) void out_kernel(
    const float* __restrict__ qin, const float* __restrict__ q_mask,
    float* __restrict__ out)
{
    extern __shared__ float dynbuf[];
    float (*qs)[QPAD] = (float(*)[QPAD])dynbuf;
    float (*kvs)[64]  = (float(*)[64])(dynbuf + 128 * QPAD);
    float* ksum_s     = dynbuf + 128 * QPAD + 64 * 64;
    float* div_s      = ksum_s + 64;

    const int nh = blockIdx.x;
    const int n = nh >> 3, h = nh & 7;
    const int l0 = blockIdx.y * 128;
    const int t = threadIdx.x;
    const int tx = t & 7;
    const int tyg = t >> 3;   // 0..15

    const float4* kvg = (const float4*)&g_kv[nh * 4096];
    #pragma unroll
    for (int e = 0; e < 8; e++)
        ((float4*)kvs)[t + e * 128] = kvg[t + e * 128];
    if (t < 64) ksum_s[t] = g_ksum[nh * 64 + t];

    #pragma unroll
    for (int e = 0; e < 16; e++) {
        int idx = t + e * 128;
        int l = idx >> 4, c4 = (idx & 15) * 4;
        float m = q_mask[n * LL + l0 + l];
        size_t g = (((size_t)(n * LL + l0 + l)) * HH + h) * DD + c4;
        float4 x = *(const float4*)&qin[g];
        *(float4*)&qs[l][c4] = make_float4(fmap(x.x) * m, fmap(x.y) * m,
                                           fmap(x.z) * m, fmap(x.w) * m);
    }
    __syncthreads();

    {
        float p = 0.f;
        #pragma unroll 16
        for (int d = 0; d < 64; d++)
            p += qs[t][d] * ksum_s[d];
        div_s[t] = 1.f / (p + EPS);
    }
    __syncthreads();

    u64 acc2[8][4] = {};
    #pragma unroll 2
    for (int d4 = 0; d4 < 64; d4 += 4) {
        float4 a[8];
        #pragma unroll
        for (int i = 0; i < 8; i++) {
            int row = (i < 4) ? (tyg * 4 + i) : (64 + tyg * 4 + i - 4);
            a[i] = *(const float4*)&qs[row][d4];
        }
        #pragma unroll
        for (int dd = 0; dd < 4; dd++) {
            float4 b0 = *(const float4*)&kvs[d4 + dd][tx * 4];
            float4 b1 = *(const float4*)&kvs[d4 + dd][32 + tx * 4];
            u64 b2[4];
            b2[0] = ((const u64*)&b0)[0];
            b2[1] = ((const u64*)&b0)[1];
            b2[2] = ((const u64*)&b1)[0];
            b2[3] = ((const u64*)&b1)[1];
            #pragma unroll
            for (int i = 0; i < 8; i++) {
                u64 as = splat2(((const float*)&a[i])[dd]);
                #pragma unroll
                for (int j = 0; j < 4; j++)
                    acc2[i][j] = ffma2(as, b2[j], acc2[i][j]);
            }
        }
    }

    #pragma unroll
    for (int i = 0; i < 8; i++) {
        int rl = (i < 4) ? (tyg * 4 + i) : (64 + tyg * 4 + i - 4);
        int l = l0 + rl;
        float dv = div_s[rl];
        float4 f0, f1;
        ((u64*)&f0)[0] = acc2[i][0];
        ((u64*)&f0)[1] = acc2[i][1];
        ((u64*)&f1)[0] = acc2[i][2];
        ((u64*)&f1)[1] = acc2[i][3];
        f0.x *= dv; f0.y *= dv; f0.z *= dv; f0.w *= dv;
        f1.x *= dv; f1.y *= dv; f1.z *= dv; f1.w *= dv;
        size_t g = (((size_t)(n * LL + l)) * HH + h) * DD;
        *(float4*)&out[g + tx * 4] = f0;
        *(float4*)&out[g + 32 + tx * 4] = f1;
    }
}

extern "C" void kernel_launch(void* const* d_in, const int* in_sizes, int n_in,
                              void* d_out, int out_size)
{
    const float* q   = (const float*)d_in[0];
    const float* k   = (const float*)d_in[1];
    const float* v   = (const float*)d_in[2];
    const float* qm  = (const float*)d_in[3];
    const float* kvm = (const float*)d_in[4];
    float* out = (float*)d_out;

    static bool attr_done = false;
    if (!attr_done) {
        cudaFuncSetAttribute(out_kernel,
                             cudaFuncAttributeMaxDynamicSharedMemorySize,
                             OUT_SMEM_BYTES);
        attr_done = true;
    }

    kv_partial_kernel<<<dim3(NH, CH), 128>>>(k, v, kvm);
    kv_reduce_kernel<<<(NH * PART_STRIDE) / 256, 256>>>();
    out_kernel<<<dim3(NH, 64), 128, OUT_SMEM_BYTES>>>(q, qm, out);
}

// round 8
// speedup vs baseline: 1.1018x; 1.1018x over previous
#include <cuda_runtime.h>

#define NB 4
#define LL 8192
#define SSZ 8192
#define HH 8
#define DD 64
#define NH (NB * HH)
#define CHA 64           // s-chunks per (n,h); 128 s per chunk
#define PART_STRIDE 4160 // 4096 kv + 64 ksum
#define EPS 1e-6f
#define QPAD 68

typedef unsigned long long u64;

__device__ float g_part[NH * CHA * PART_STRIDE];
__device__ float g_kv[NH * DD * DD];
__device__ float g_ksum[NH * DD];

__device__ __forceinline__ float fmap(float x) {
    return x > 0.f ? x + 1.f : __expf(x);
}

__device__ __forceinline__ u64 splat2(float a) {
    u64 r;
    asm("mov.b64 %0, {%1, %1};" : "=l"(r) : "f"(a));
    return r;
}

__device__ __forceinline__ u64 ffma2(u64 a, u64 b, u64 c) {
    u64 d;
    asm("fma.rn.f32x2 %0, %1, %2, %3;" : "=l"(d) : "l"(a), "l"(b), "l"(c));
    return d;
}

// Kernel A: partial kv over a 128-s chunk (round-6 body, more CTAs).
// 64 threads, 8 CTAs/SM. 8x8 fragment split 4+4 (no 128B bank wrap).
__global__ __launch_bounds__(64, 8) void kv_partial_kernel(
    const float* __restrict__ kin, const float* __restrict__ vin,
    const float* __restrict__ kv_mask)
{
    __shared__ float ks[32][64];
    __shared__ float vs[32][64];

    const int nh = blockIdx.x;
    const int n = nh >> 3, h = nh & 7;
    const int s0 = blockIdx.y * 128;
    const int t = threadIdx.x;
    const int tx = t & 7, ty = t >> 3;

    u64 acc2[8][4] = {};
    float ksl = 0.f;

    #pragma unroll 1
    for (int tile = 0; tile < 4; tile++) {
        #pragma unroll
        for (int e = 0; e < 8; e++) {
            int idx = t + e * 64;
            int r = idx >> 4, c4 = (idx & 15) * 4;
            int s = s0 + tile * 32 + r;
            float m = kv_mask[n * SSZ + s];
            size_t g = (((size_t)(n * SSZ + s)) * HH + h) * DD + c4;
            float4 kq = *(const float4*)&kin[g];
            float4 vq = *(const float4*)&vin[g];
            *(float4*)&ks[r][c4] = make_float4(fmap(kq.x) * m, fmap(kq.y) * m,
                                               fmap(kq.z) * m, fmap(kq.w) * m);
            *(float4*)&vs[r][c4] = make_float4(vq.x * m, vq.y * m,
                                               vq.z * m, vq.w * m);
        }
        __syncthreads();

        #pragma unroll 4
        for (int s = 0; s < 32; s++) {
            float4 a0 = *(const float4*)&ks[s][ty * 4];
            float4 a1 = *(const float4*)&ks[s][32 + ty * 4];
            float4 b0 = *(const float4*)&vs[s][tx * 4];
            float4 b1 = *(const float4*)&vs[s][32 + tx * 4];
            ksl += ks[s][t];
            float a[8] = {a0.x, a0.y, a0.z, a0.w, a1.x, a1.y, a1.z, a1.w};
            u64 b2[4];
            b2[0] = ((const u64*)&b0)[0];
            b2[1] = ((const u64*)&b0)[1];
            b2[2] = ((const u64*)&b1)[0];
            b2[3] = ((const u64*)&b1)[1];
            #pragma unroll
            for (int i = 0; i < 8; i++) {
                u64 as = splat2(a[i]);
                #pragma unroll
                for (int j = 0; j < 4; j++)
                    acc2[i][j] = ffma2(as, b2[j], acc2[i][j]);
            }
        }
        __syncthreads();
    }

    float* part = &g_part[(nh * CHA + blockIdx.y) * PART_STRIDE];
    #pragma unroll
    for (int i = 0; i < 8; i++) {
        int row = (i < 4) ? (ty * 4 + i) : (32 + ty * 4 + i - 4);
        float4 f0, f1;
        ((u64*)&f0)[0] = acc2[i][0];
        ((u64*)&f0)[1] = acc2[i][1];
        ((u64*)&f1)[0] = acc2[i][2];
        ((u64*)&f1)[1] = acc2[i][3];
        *(float4*)&part[row * 64 + tx * 4] = f0;
        *(float4*)&part[row * 64 + 32 + tx * 4] = f1;
    }
    part[4096 + t] = ksl;
}

// Reduce 64 partials -> final kv + ksum. 520 blocks x 256 threads.
__global__ __launch_bounds__(256) void kv_reduce_kernel() {
    int idx = blockIdx.x * 256 + threadIdx.x;
    int nh = idx / PART_STRIDE;
    int el = idx - nh * PART_STRIDE;
    float s = 0.f;
    #pragma unroll 8
    for (int ch = 0; ch < CHA; ch++)
        s += g_part[(nh * CHA + ch) * PART_STRIDE + el];
    if (el < 4096) g_kv[nh * 4096 + el] = s;
    else           g_ksum[nh * 64 + el - 4096] = s;
}

// Kernel B: out = (qf . kv) / (qf . ksum + eps). 128 threads, 64 l-rows/CTA.
// smem ~34KB -> 5 CTAs/SM -> 20 warps.
#define OUT_SMEM_BYTES (64 * QPAD * 4 + 64 * 64 * 4 + 64 * 4 + 64 * 4)

__global__ __launch_bounds__(128, 5) void out_kernel(
    const float* __restrict__ qin, const float* __restrict__ q_mask,
    float* __restrict__ out)
{
    extern __shared__ float dynbuf[];
    float (*qs)[QPAD] = (float(*)[QPAD])dynbuf;                 // 64*68
    float (*kvs)[64]  = (float(*)[64])(dynbuf + 64 * QPAD);    // 64*64
    float* ksum_s     = dynbuf + 64 * QPAD + 64 * 64;          // 64
    float* div_s      = ksum_s + 64;                           // 64

    const int nh = blockIdx.x;
    const int n = nh >> 3, h = nh & 7;
    const int l0 = blockIdx.y * 64;
    const int t = threadIdx.x;
    const int tx = t & 7;
    const int tyg = t >> 3;   // 0..15

    const float4* kvg = (const float4*)&g_kv[nh * 4096];
    #pragma unroll
    for (int e = 0; e < 8; e++)
        ((float4*)kvs)[t + e * 128] = kvg[t + e * 128];
    if (t < 64) ksum_s[t] = g_ksum[nh * 64 + t];

    #pragma unroll
    for (int e = 0; e < 8; e++) {
        int idx = t + e * 128;
        int l = idx >> 4, c4 = (idx & 15) * 4;
        float m = q_mask[n * LL + l0 + l];
        size_t g = (((size_t)(n * LL + l0 + l)) * HH + h) * DD + c4;
        float4 x = *(const float4*)&qin[g];
        *(float4*)&qs[l][c4] = make_float4(fmap(x.x) * m, fmap(x.y) * m,
                                           fmap(x.z) * m, fmap(x.w) * m);
    }
    __syncthreads();

    if (t < 64) {
        float p = 0.f;
        #pragma unroll 16
        for (int d = 0; d < 64; d++)
            p += qs[t][d] * ksum_s[d];
        div_s[t] = 1.f / (p + EPS);
    }
    __syncthreads();

    u64 acc2[4][4] = {};
    #pragma unroll 2
    for (int d4 = 0; d4 < 64; d4 += 4) {
        float4 a[4];
        #pragma unroll
        for (int i = 0; i < 4; i++)
            a[i] = *(const float4*)&qs[tyg * 4 + i][d4];
        #pragma unroll
        for (int dd = 0; dd < 4; dd++) {
            float4 b0 = *(const float4*)&kvs[d4 + dd][tx * 4];
            float4 b1 = *(const float4*)&kvs[d4 + dd][32 + tx * 4];
            u64 b2[4];
            b2[0] = ((const u64*)&b0)[0];
            b2[1] = ((const u64*)&b0)[1];
            b2[2] = ((const u64*)&b1)[0];
            b2[3] = ((const u64*)&b1)[1];
            #pragma unroll
            for (int i = 0; i < 4; i++) {
                u64 as = splat2(((const float*)&a[i])[dd]);
                #pragma unroll
                for (int j = 0; j < 4; j++)
                    acc2[i][j] = ffma2(as, b2[j], acc2[i][j]);
            }
        }
    }

    #pragma unroll
    for (int i = 0; i < 4; i++) {
        int rl = tyg * 4 + i;
        int l = l0 + rl;
        float dv = div_s[rl];
        float4 f0, f1;
        ((u64*)&f0)[0] = acc2[i][0];
        ((u64*)&f0)[1] = acc2[i][1];
        ((u64*)&f1)[0] = acc2[i][2];
        ((u64*)&f1)[1] = acc2[i][3];
        f0.x *= dv; f0.y *= dv; f0.z *= dv; f0.w *= dv;
        f1.x *= dv; f1.y *= dv; f1.z *= dv; f1.w *= dv;
        size_t g = (((size_t)(n * LL + l)) * HH + h) * DD;
        *(float4*)&out[g + tx * 4] = f0;
        *(float4*)&out[g + 32 + tx * 4] = f1;
    }
}

extern "C" void kernel_launch(void* const* d_in, const int* in_sizes, int n_in,
                              void* d_out, int out_size)
{
    const float* q   = (const float*)d_in[0];
    const float* k   = (const float*)d_in[1];
    const float* v   = (const float*)d_in[2];
    const float* qm  = (const float*)d_in[3];
    const float* kvm = (const float*)d_in[4];
    float* out = (float*)d_out;

    static bool attr_done = false;
    if (!attr_done) {
        cudaFuncSetAttribute(out_kernel,
                             cudaFuncAttributeMaxDynamicSharedMemorySize,
                             OUT_SMEM_BYTES);
        attr_done = true;
    }

    kv_partial_kernel<<<dim3(NH, CHA), 64>>>(k, v, kvm);
    kv_reduce_kernel<<<(NH * PART_STRIDE) / 256, 256>>>();
    out_kernel<<<dim3(NH, 128), 128, OUT_SMEM_BYTES>>>(q, qm, out);
}

// round 10
// speedup vs baseline: 1.2170x; 1.1045x over previous
#include <cuda_runtime.h>
#include <cuda_bf16.h>
#include <cstdint>

#define NB 4
#define LL 8192
#define SSZ 8192
#define HH 8
#define DD 64
#define NH (NB * HH)
#define CHA 64           // s-chunks per (n,h); 128 s per chunk
#define PART_STRIDE 4160 // 4096 kv + 64 ksum
#define EPS 1e-6f
#define BR 72            // B rows: 64 kv^T + 1 ksum + 7 zero
#define BSTR 144         // smem row stride in bytes (72 bf16)

typedef unsigned long long u64;
typedef unsigned int u32;

__device__ float g_part[NH * CHA * PART_STRIDE];
// bf16 split kv^T (+ksum row 64; rows 65-71 never written -> stay zero)
__device__ __nv_bfloat16 g_kvbf_hi[NH * BR * DD];
__device__ __nv_bfloat16 g_kvbf_lo[NH * BR * DD];

__device__ __forceinline__ float fmap(float x) {
    return x > 0.f ? x + 1.f : __expf(x);
}

__device__ __forceinline__ u64 splat2(float a) {
    u64 r;
    asm("mov.b64 %0, {%1, %1};" : "=l"(r) : "f"(a));
    return r;
}

__device__ __forceinline__ u64 ffma2(u64 a, u64 b, u64 c) {
    u64 d;
    asm("fma.rn.f32x2 %0, %1, %2, %3;" : "=l"(d) : "l"(a), "l"(b), "l"(c));
    return d;
}

__device__ __forceinline__ u32 smem_u32(const void* p) {
    u32 a;
    asm("{ .reg .u64 t; cvta.to.shared.u64 t, %1; cvt.u32.u64 %0, t; }"
        : "=r"(a) : "l"(p));
    return a;
}

__device__ __forceinline__ void ldsm4(u32* r, u32 addr) {
    asm volatile("ldmatrix.sync.aligned.m8n8.x4.shared.b16 {%0,%1,%2,%3}, [%4];"
                 : "=r"(r[0]), "=r"(r[1]), "=r"(r[2]), "=r"(r[3]) : "r"(addr));
}

__device__ __forceinline__ void ldsm2(u32* r, u32 addr) {
    asm volatile("ldmatrix.sync.aligned.m8n8.x2.shared.b16 {%0,%1}, [%2];"
                 : "=r"(r[0]), "=r"(r[1]) : "r"(addr));
}

__device__ __forceinline__ void mma_bf16(float* c, const u32* a, u32 b0, u32 b1) {
    asm volatile(
        "mma.sync.aligned.m16n8k16.row.col.f32.bf16.bf16.f32 "
        "{%0,%1,%2,%3}, {%4,%5,%6,%7}, {%8,%9}, {%0,%1,%2,%3};"
        : "+f"(c[0]), "+f"(c[1]), "+f"(c[2]), "+f"(c[3])
        : "r"(a[0]), "r"(a[1]), "r"(a[2]), "r"(a[3]), "r"(b0), "r"(b1));
}

__device__ __forceinline__ unsigned short bfbits(float x) {
    __nv_bfloat16 b = __float2bfloat16_rn(x);
    return *(unsigned short*)&b;
}

// ---------------- Kernel A: scalar FFMA2 (round-8, passing) ----------------
__global__ __launch_bounds__(64, 8) void kv_partial_kernel(
    const float* __restrict__ kin, const float* __restrict__ vin,
    const float* __restrict__ kv_mask)
{
    __shared__ float ks[32][64];
    __shared__ float vs[32][64];

    const int nh = blockIdx.x;
    const int n = nh >> 3, h = nh & 7;
    const int s0 = blockIdx.y * 128;
    const int t = threadIdx.x;
    const int tx = t & 7, ty = t >> 3;

    u64 acc2[8][4] = {};
    float ksl = 0.f;

    #pragma unroll 1
    for (int tile = 0; tile < 4; tile++) {
        #pragma unroll
        for (int e = 0; e < 8; e++) {
            int idx = t + e * 64;
            int r = idx >> 4, c4 = (idx & 15) * 4;
            int s = s0 + tile * 32 + r;
            float m = kv_mask[n * SSZ + s];
            size_t g = (((size_t)(n * SSZ + s)) * HH + h) * DD + c4;
            float4 kq = *(const float4*)&kin[g];
            float4 vq = *(const float4*)&vin[g];
            *(float4*)&ks[r][c4] = make_float4(fmap(kq.x) * m, fmap(kq.y) * m,
                                               fmap(kq.z) * m, fmap(kq.w) * m);
            *(float4*)&vs[r][c4] = make_float4(vq.x * m, vq.y * m,
                                               vq.z * m, vq.w * m);
        }
        __syncthreads();

        #pragma unroll 4
        for (int s = 0; s < 32; s++) {
            float4 a0 = *(const float4*)&ks[s][ty * 4];
            float4 a1 = *(const float4*)&ks[s][32 + ty * 4];
            float4 b0 = *(const float4*)&vs[s][tx * 4];
            float4 b1 = *(const float4*)&vs[s][32 + tx * 4];
            ksl += ks[s][t];
            float a[8] = {a0.x, a0.y, a0.z, a0.w, a1.x, a1.y, a1.z, a1.w};
            u64 b2[4];
            b2[0] = ((const u64*)&b0)[0];
            b2[1] = ((const u64*)&b0)[1];
            b2[2] = ((const u64*)&b1)[0];
            b2[3] = ((const u64*)&b1)[1];
            #pragma unroll
            for (int i = 0; i < 8; i++) {
                u64 as = splat2(a[i]);
                #pragma unroll
                for (int j = 0; j < 4; j++)
                    acc2[i][j] = ffma2(as, b2[j], acc2[i][j]);
            }
        }
        __syncthreads();
    }

    float* part = &g_part[(nh * CHA + blockIdx.y) * PART_STRIDE];
    #pragma unroll
    for (int i = 0; i < 8; i++) {
        int row = (i < 4) ? (ty * 4 + i) : (32 + ty * 4 + i - 4);
        float4 f0, f1;
        ((u64*)&f0)[0] = acc2[i][0];
        ((u64*)&f0)[1] = acc2[i][1];
        ((u64*)&f1)[0] = acc2[i][2];
        ((u64*)&f1)[1] = acc2[i][3];
        *(float4*)&part[row * 64 + tx * 4] = f0;
        *(float4*)&part[row * 64 + 32 + tx * 4] = f1;
    }
    part[4096 + t] = ksl;
}

// ---------------- Reduce: fp32 sum -> transposed bf16 hi/lo B tiles ----------------
__global__ __launch_bounds__(256) void kv_reduce_kernel() {
    int idx = blockIdx.x * 256 + threadIdx.x;
    int nh = idx / PART_STRIDE;
    int el = idx - nh * PART_STRIDE;
    float s = 0.f;
    #pragma unroll 8
    for (int ch = 0; ch < CHA; ch++)
        s += g_part[(nh * CHA + ch) * PART_STRIDE + el];

    __nv_bfloat16 hi = __float2bfloat16_rn(s);
    __nv_bfloat16 lo = __float2bfloat16_rn(s - __bfloat162float(hi));

    int dst;
    if (el < 4096) {
        int d = el >> 6, v = el & 63;
        dst = nh * (BR * DD) + v * 64 + d;      // transposed: row v (n), col d (k)
    } else {
        int d = el - 4096;
        dst = nh * (BR * DD) + 64 * 64 + d;     // ksum -> B row 64
    }
    g_kvbf_hi[dst] = hi;
    g_kvbf_lo[dst] = lo;
}

// ---------------- Kernel B: HMMA (mma.sync bf16-split) ----------------
// Per CTA: 128 l-rows x N=72 x K=64. 256 threads = 8 warps, one m16 stripe each.
#define SM_AHI 0
#define SM_ALO (128 * BSTR)
#define SM_BHI (2 * 128 * BSTR)
#define SM_BLO (SM_BHI + BR * BSTR)
#define OUT_SMEM_BYTES (SM_BLO + BR * BSTR)   // 57600

__global__ __launch_bounds__(256) void out_mma_kernel(
    const float* __restrict__ qin, const float* __restrict__ q_mask,
    float* __restrict__ out)
{
    extern __shared__ char smem[];
    const u32 sb = smem_u32(smem);

    const int nh = blockIdx.x;
    const int n = nh >> 3, h = nh & 7;
    const int l0 = blockIdx.y * 128;
    const int t = threadIdx.x;
    const int lane = t & 31, w = t >> 5;

    // stage B (72 rows x 64 bf16, hi/lo), row stride 144B
    {
        const u32* ghi = (const u32*)&g_kvbf_hi[nh * (BR * DD)];
        const u32* glo = (const u32*)&g_kvbf_lo[nh * (BR * DD)];
        #pragma unroll
        for (int e = 0; e < 9; e++) {           // 9*256 = 2304 u32 = 72*32
            int idx = t + e * 256;
            int row = idx >> 5, c = idx & 31;
            *(u32*)(smem + SM_BHI + row * BSTR + c * 4) = ghi[idx];
            *(u32*)(smem + SM_BLO + row * BSTR + c * 4) = glo[idx];
        }
    }

    // stage A: featurize q, split hi/lo, row stride 144B
    #pragma unroll
    for (int e = 0; e < 8; e++) {
        int idx = t + e * 256;                  // 2048 float4 groups
        int l = idx >> 4, c4 = (idx & 15) * 4;
        float m = q_mask[n * LL + l0 + l];
        size_t g = (((size_t)(n * LL + l0 + l)) * HH + h) * DD + c4;
        float4 x = *(const float4*)&qin[g];
        float f[4] = {fmap(x.x) * m, fmap(x.y) * m, fmap(x.z) * m, fmap(x.w) * m};
        unsigned short hb[4], lb[4];
        #pragma unroll
        for (int j = 0; j < 4; j++) {
            hb[j] = bfbits(f[j]);
            __nv_bfloat16 hv = *(__nv_bfloat16*)&hb[j];
            lb[j] = bfbits(f[j] - __bfloat162float(hv));
        }
        u32 off = l * BSTR + c4 * 2;            // 8B-aligned
        *(u32*)(smem + SM_AHI + off)     = (u32)hb[0] | ((u32)hb[1] << 16);
        *(u32*)(smem + SM_AHI + off + 4) = (u32)hb[2] | ((u32)hb[3] << 16);
        *(u32*)(smem + SM_ALO + off)     = (u32)lb[0] | ((u32)lb[1] << 16);
        *(u32*)(smem + SM_ALO + off + 4) = (u32)lb[2] | ((u32)lb[3] << 16);
    }
    __syncthreads();

    // per-warp GEMM: m16 stripe at w*16, 9 n8 tiles, K=64 in 4 k16 steps
    const int mbase = w * 16;
    float acc[9][4] = {};

    const u32 a_off = (u32)(mbase + (lane & 15)) * BSTR + (u32)(lane >> 4) * 16;
    const int bi = lane & 7, bg = lane >> 3;
    const u32 b4_off = (u32)(bi + ((bg & 2) << 2)) * BSTR + (u32)(bg & 1) * 16;
    const u32 b2_off = (u32)(64 + bi) * BSTR + (u32)(bg & 1) * 16;

    #pragma unroll
    for (int kk = 0; kk < 4; kk++) {
        const u32 koff = kk * 32;               // k16 * 2 bytes
        u32 ahi[4], alo[4];
        ldsm4(ahi, sb + SM_AHI + a_off + koff);
        ldsm4(alo, sb + SM_ALO + a_off + koff);

        #pragma unroll
        for (int p = 0; p < 4; p++) {           // n-tile pairs {2p, 2p+1}
            u32 bh[4], bl[4];
            u32 ba = (u32)(p * 16) * BSTR + b4_off + koff;
            ldsm4(bh, sb + SM_BHI + ba);
            ldsm4(bl, sb + SM_BLO + ba);
            mma_bf16(acc[2 * p],     ahi, bh[0], bh[1]);
            mma_bf16(acc[2 * p],     ahi, bl[0], bl[1]);
            mma_bf16(acc[2 * p],     alo, bh[0], bh[1]);
            mma_bf16(acc[2 * p + 1], ahi, bh[2], bh[3]);
            mma_bf16(acc[2 * p + 1], ahi, bl[2], bl[3]);
            mma_bf16(acc[2 * p + 1], alo, bh[2], bh[3]);
        }
        {                                        // n-tile 8 (ksum col 64)
            u32 bh[2], bl[2];
            ldsm2(bh, sb + SM_BHI + b2_off + koff);
            ldsm2(bl, sb + SM_BLO + b2_off + koff);
            mma_bf16(acc[8], ahi, bh[0], bh[1]);
            mma_bf16(acc[8], ahi, bl[0], bl[1]);
            mma_bf16(acc[8], alo, bh[0], bh[1]);
        }
    }

    // epilogue: normalizer = D col 64 (tile 8, local col 0 -> lane%4==0)
    float n0 = __shfl_sync(0xffffffffu, acc[8][0], lane & ~3);
    float n1 = __shfl_sync(0xffffffffu, acc[8][2], lane & ~3);
    float dv0 = 1.f / (n0 + EPS);
    float dv1 = 1.f / (n1 + EPS);

    const int r0 = l0 + mbase + (lane >> 2);
    const int col = 2 * (lane & 3);
    size_t g0 = (((size_t)(n * LL + r0)) * HH + h) * DD;
    size_t g1 = g0 + (size_t)8 * HH * DD;

    #pragma unroll
    for (int nt = 0; nt < 8; nt++) {
        *(float2*)&out[g0 + nt * 8 + col] =
            make_float2(acc[nt][0] * dv0, acc[nt][1] * dv0);
        *(float2*)&out[g1 + nt * 8 + col] =
            make_float2(acc[nt][2] * dv1, acc[nt][3] * dv1);
    }
}

extern "C" void kernel_launch(void* const* d_in, const int* in_sizes, int n_in,
                              void* d_out, int out_size)
{
    const float* q   = (const float*)d_in[0];
    const float* k   = (const float*)d_in[1];
    const float* v   = (const float*)d_in[2];
    const float* qm  = (const float*)d_in[3];
    const float* kvm = (const float*)d_in[4];
    float* out = (float*)d_out;

    static bool attr_done = false;
    if (!attr_done) {
        cudaFuncSetAttribute(out_mma_kernel,
                             cudaFuncAttributeMaxDynamicSharedMemorySize,
                             OUT_SMEM_BYTES);
        attr_done = true;
    }

    kv_partial_kernel<<<dim3(NH, CHA), 64>>>(k, v, kvm);
    kv_reduce_kernel<<<(NH * PART_STRIDE) / 256, 256>>>();
    out_mma_kernel<<<dim3(NH, 64), 256, OUT_SMEM_BYTES>>>(q, qm, out);
}

// round 11
// speedup vs baseline: 1.2443x; 1.0225x over previous
#include <cuda_runtime.h>
#include <cuda_bf16.h>
#include <cstdint>

#define NB 4
#define LL 8192
#define SSZ 8192
#define HH 8
#define DD 64
#define NH (NB * HH)
#define CHA 32           // s-chunks per (n,h); 256 s per chunk
#define PART_STRIDE 4160 // 4096 kv + 64 ksum
#define EPS 1e-6f
#define BR 72            // B rows: 64 kv^T + 1 ksum + 7 zero
#define BSTR 144         // smem row stride bytes (72 bf16)
#define SEL 72           // staging row stride elements

typedef unsigned long long u64;
typedef unsigned int u32;

__device__ float g_part[NH * CHA * PART_STRIDE];
__device__ __nv_bfloat16 g_kvbf_hi[NH * BR * DD];
__device__ __nv_bfloat16 g_kvbf_lo[NH * BR * DD];

__device__ __forceinline__ float fmap(float x) {
    return x > 0.f ? x + 1.f : __expf(x);
}

__device__ __forceinline__ u32 smem_u32(const void* p) {
    u32 a;
    asm("{ .reg .u64 t; cvta.to.shared.u64 t, %1; cvt.u32.u64 %0, t; }"
        : "=r"(a) : "l"(p));
    return a;
}

__device__ __forceinline__ void ldsm4(u32* r, u32 addr) {
    asm volatile("ldmatrix.sync.aligned.m8n8.x4.shared.b16 {%0,%1,%2,%3}, [%4];"
                 : "=r"(r[0]), "=r"(r[1]), "=r"(r[2]), "=r"(r[3]) : "r"(addr));
}

__device__ __forceinline__ void ldsm4t(u32* r, u32 addr) {
    asm volatile("ldmatrix.sync.aligned.m8n8.x4.trans.shared.b16 {%0,%1,%2,%3}, [%4];"
                 : "=r"(r[0]), "=r"(r[1]), "=r"(r[2]), "=r"(r[3]) : "r"(addr));
}

__device__ __forceinline__ void ldsm2(u32* r, u32 addr) {
    asm volatile("ldmatrix.sync.aligned.m8n8.x2.shared.b16 {%0,%1}, [%2];"
                 : "=r"(r[0]), "=r"(r[1]) : "r"(addr));
}

__device__ __forceinline__ void ldsm2t(u32* r, u32 addr) {
    asm volatile("ldmatrix.sync.aligned.m8n8.x2.trans.shared.b16 {%0,%1}, [%2];"
                 : "=r"(r[0]), "=r"(r[1]) : "r"(addr));
}

__device__ __forceinline__ void mma_bf16(float* c, const u32* a, u32 b0, u32 b1) {
    asm volatile(
        "mma.sync.aligned.m16n8k16.row.col.f32.bf16.bf16.f32 "
        "{%0,%1,%2,%3}, {%4,%5,%6,%7}, {%8,%9}, {%0,%1,%2,%3};"
        : "+f"(c[0]), "+f"(c[1]), "+f"(c[2]), "+f"(c[3])
        : "r"(a[0]), "r"(a[1]), "r"(a[2]), "r"(a[3]), "r"(b0), "r"(b1));
}

__device__ __forceinline__ unsigned short bfbits(float x) {
    __nv_bfloat16 b = __float2bfloat16_rn(x);
    return *(unsigned short*)&b;
}

__device__ __forceinline__ void split2(float f0, float f1, u32& hi, u32& lo) {
    unsigned short h0 = bfbits(f0), h1 = bfbits(f1);
    __nv_bfloat16 hv0 = *(__nv_bfloat16*)&h0, hv1 = *(__nv_bfloat16*)&h1;
    unsigned short l0 = bfbits(f0 - __bfloat162float(hv0));
    unsigned short l1 = bfbits(f1 - __bfloat162float(hv1));
    hi = (u32)h0 | ((u32)h1 << 16);
    lo = (u32)l0 | ((u32)l1 << 16);
}

// ---------------- Kernel A: HMMA kv partial over 256-s chunk ----------------
// 128 threads = 4 warps; warp w owns d-stripe [w*16, w*16+16) x 9 n8 tiles (N=72).
// A = kf^T via ldmatrix.trans of [s][d] tile; B = vm^T via trans of [s][v] tile.
// B col 64 = 1.0 -> D col 64 = ksum.
__global__ __launch_bounds__(128) void kv_mma_kernel(
    const float* __restrict__ kin, const float* __restrict__ vin,
    const float* __restrict__ kv_mask)
{
    __shared__ __nv_bfloat16 khi[32 * SEL], klo[32 * SEL];
    __shared__ __nv_bfloat16 vhi[32 * SEL], vlo[32 * SEL];

    const int nh = blockIdx.x;
    const int n = nh >> 3, h = nh & 7;
    const int s0 = blockIdx.y * 256;
    const int t = threadIdx.x;
    const int lane = t & 31, w = t >> 5;

    const u32 sb_khi = smem_u32(khi), sb_klo = smem_u32(klo);
    const u32 sb_vhi = smem_u32(vhi), sb_vlo = smem_u32(vlo);

    // ones column (v cols 64-71): col64 = 1.0, rest 0; written once
    if (t < 32) {
        *(uint4*)&vhi[t * SEL + 64] = make_uint4(0x3F80u, 0u, 0u, 0u);
        *(uint4*)&vlo[t * SEL + 64] = make_uint4(0u, 0u, 0u, 0u);
    }

    float acc[9][4] = {};

    #pragma unroll 1
    for (int tile = 0; tile < 8; tile++) {
        // stage 32 s-rows x 64 cols, featurized + split
        #pragma unroll
        for (int e = 0; e < 4; e++) {
            int idx = t + e * 128;
            int r = idx >> 4, c4 = (idx & 15) * 4;
            int s = s0 + tile * 32 + r;
            float m = kv_mask[n * SSZ + s];
            size_t g = (((size_t)(n * SSZ + s)) * HH + h) * DD + c4;
            float4 kq = *(const float4*)&kin[g];
            float4 vq = *(const float4*)&vin[g];
            u32 kh0, kl0, kh1, kl1, vh0, vl0, vh1, vl1;
            split2(fmap(kq.x) * m, fmap(kq.y) * m, kh0, kl0);
            split2(fmap(kq.z) * m, fmap(kq.w) * m, kh1, kl1);
            split2(vq.x * m, vq.y * m, vh0, vl0);
            split2(vq.z * m, vq.w * m, vh1, vl1);
            int ui = r * (SEL / 2) + (c4 >> 1);
            ((u32*)khi)[ui] = kh0; ((u32*)khi)[ui + 1] = kh1;
            ((u32*)klo)[ui] = kl0; ((u32*)klo)[ui + 1] = kl1;
            ((u32*)vhi)[ui] = vh0; ((u32*)vhi)[ui + 1] = vh1;
            ((u32*)vlo)[ui] = vl0; ((u32*)vlo)[ui + 1] = vl1;
        }
        __syncthreads();

        #pragma unroll
        for (int kk = 0; kk < 2; kk++) {
            // A fragment (m16k16, trans): lanes 0-7/8-15 -> k0-7 (m0/m8),
            // lanes 16-23/24-31 -> k8-15 (m0/m8)
            u32 arow = (u32)((lane & 7) + ((lane >> 4) & 1) * 8 + kk * 16);
            u32 acol = (u32)(w * 16 + ((lane >> 3) & 1) * 8);
            u32 aoff = arow * BSTR + acol * 2;
            u32 ahi[4], alo[4];
            ldsm4t(ahi, sb_khi + aoff);
            ldsm4t(alo, sb_klo + aoff);

            // B fragments (n8k16 x2, trans): lanes 0-7 -> k0-7, 8-15 -> k8-15 (n0);
            // 16-23/24-31 same for n+8
            u32 brow = (u32)((lane & 7) + ((lane >> 3) & 1) * 8 + kk * 16);
            #pragma unroll
            for (int p = 0; p < 4; p++) {
                u32 boff = brow * BSTR + (u32)(p * 16 + ((lane >> 4) & 1) * 8) * 2;
                u32 bh[4], bl[4];
                ldsm4t(bh, sb_vhi + boff);
                ldsm4t(bl, sb_vlo + boff);
                mma_bf16(acc[2 * p],     ahi, bh[0], bh[1]);
                mma_bf16(acc[2 * p],     ahi, bl[0], bl[1]);
                mma_bf16(acc[2 * p],     alo, bh[0], bh[1]);
                mma_bf16(acc[2 * p + 1], ahi, bh[2], bh[3]);
                mma_bf16(acc[2 * p + 1], ahi, bl[2], bl[3]);
                mma_bf16(acc[2 * p + 1], alo, bh[2], bh[3]);
            }
            {   // ksum tile (n = 64-71)
                u32 b2off = brow * BSTR + 64 * 2;
                u32 bh[2], bl[2];
                ldsm2t(bh, sb_vhi + b2off);
                ldsm2t(bl, sb_vlo + b2off);
                mma_bf16(acc[8], ahi, bh[0], bh[1]);
                mma_bf16(acc[8], ahi, bl[0], bl[1]);
                mma_bf16(acc[8], alo, bh[0], bh[1]);
            }
        }
        __syncthreads();
    }

    // write partials: D[m=d][n=v]; lane row = lane>>2 (+8), col = 2*(lane&3)
    float* part = &g_part[(nh * CHA + blockIdx.y) * PART_STRIDE];
    const int r0 = w * 16 + (lane >> 2);
    const int col = 2 * (lane & 3);
    #pragma unroll
    for (int nt = 0; nt < 8; nt++) {
        *(float2*)&part[r0 * 64 + nt * 8 + col] = make_float2(acc[nt][0], acc[nt][1]);
        *(float2*)&part[(r0 + 8) * 64 + nt * 8 + col] = make_float2(acc[nt][2], acc[nt][3]);
    }
    if ((lane & 3) == 0) {          // D col 64 = ksum
        part[4096 + r0] = acc[8][0];
        part[4096 + r0 + 8] = acc[8][2];
    }
}

// ---------------- Reduce: fp32 sum -> transposed bf16 hi/lo B tiles ----------------
__global__ __launch_bounds__(256) void kv_reduce_kernel() {
    int idx = blockIdx.x * 256 + threadIdx.x;
    int nh = idx / PART_STRIDE;
    int el = idx - nh * PART_STRIDE;
    float s = 0.f;
    #pragma unroll 8
    for (int ch = 0; ch < CHA; ch++)
        s += g_part[(nh * CHA + ch) * PART_STRIDE + el];

    __nv_bfloat16 hi = __float2bfloat16_rn(s);
    __nv_bfloat16 lo = __float2bfloat16_rn(s - __bfloat162float(hi));

    int dst;
    if (el < 4096) {
        int d = el >> 6, v = el & 63;
        dst = nh * (BR * DD) + v * 64 + d;      // transposed: row v, col d
    } else {
        int d = el - 4096;
        dst = nh * (BR * DD) + 64 * 64 + d;     // ksum -> B row 64
    }
    g_kvbf_hi[dst] = hi;
    g_kvbf_lo[dst] = lo;
}

// ---------------- Kernel B: HMMA out (round-10, passing) ----------------
#define SM_AHI 0
#define SM_ALO (128 * BSTR)
#define SM_BHI (2 * 128 * BSTR)
#define SM_BLO (SM_BHI + BR * BSTR)
#define OUT_SMEM_BYTES (SM_BLO + BR * BSTR)

__global__ __launch_bounds__(256) void out_mma_kernel(
    const float* __restrict__ qin, const float* __restrict__ q_mask,
    float* __restrict__ out)
{
    extern __shared__ char smem[];
    const u32 sb = smem_u32(smem);

    const int nh = blockIdx.x;
    const int n = nh >> 3, h = nh & 7;
    const int l0 = blockIdx.y * 128;
    const int t = threadIdx.x;
    const int lane = t & 31, w = t >> 5;

    {
        const u32* ghi = (const u32*)&g_kvbf_hi[nh * (BR * DD)];
        const u32* glo = (const u32*)&g_kvbf_lo[nh * (BR * DD)];
        #pragma unroll
        for (int e = 0; e < 9; e++) {
            int idx = t + e * 256;
            int row = idx >> 5, c = idx & 31;
            *(u32*)(smem + SM_BHI + row * BSTR + c * 4) = ghi[idx];
            *(u32*)(smem + SM_BLO + row * BSTR + c * 4) = glo[idx];
        }
    }

    #pragma unroll
    for (int e = 0; e < 8; e++) {
        int idx = t + e * 256;
        int l = idx >> 4, c4 = (idx & 15) * 4;
        float m = q_mask[n * LL + l0 + l];
        size_t g = (((size_t)(n * LL + l0 + l)) * HH + h) * DD + c4;
        float4 x = *(const float4*)&qin[g];
        u32 h0, lo0, h1, lo1;
        split2(fmap(x.x) * m, fmap(x.y) * m, h0, lo0);
        split2(fmap(x.z) * m, fmap(x.w) * m, h1, lo1);
        u32 off = l * BSTR + c4 * 2;
        *(u32*)(smem + SM_AHI + off)     = h0;
        *(u32*)(smem + SM_AHI + off + 4) = h1;
        *(u32*)(smem + SM_ALO + off)     = lo0;
        *(u32*)(smem + SM_ALO + off + 4) = lo1;
    }
    __syncthreads();

    const int mbase = w * 16;
    float acc[9][4] = {};

    const u32 a_off = (u32)(mbase + (lane & 15)) * BSTR + (u32)(lane >> 4) * 16;
    const int bi = lane & 7, bg = lane >> 3;
    const u32 b4_off = (u32)(bi + ((bg & 2) << 2)) * BSTR + (u32)(bg & 1) * 16;
    const u32 b2_off = (u32)(64 + bi) * BSTR + (u32)(bg & 1) * 16;

    #pragma unroll
    for (int kk = 0; kk < 4; kk++) {
        const u32 koff = kk * 32;
        u32 ahi[4], alo[4];
        ldsm4(ahi, sb + SM_AHI + a_off + koff);
        ldsm4(alo, sb + SM_ALO + a_off + koff);

        #pragma unroll
        for (int p = 0; p < 4; p++) {
            u32 bh[4], bl[4];
            u32 ba = (u32)(p * 16) * BSTR + b4_off + koff;
            ldsm4(bh, sb + SM_BHI + ba);
            ldsm4(bl, sb + SM_BLO + ba);
            mma_bf16(acc[2 * p],     ahi, bh[0], bh[1]);
            mma_bf16(acc[2 * p],     ahi, bl[0], bl[1]);
            mma_bf16(acc[2 * p],     alo, bh[0], bh[1]);
            mma_bf16(acc[2 * p + 1], ahi, bh[2], bh[3]);
            mma_bf16(acc[2 * p + 1], ahi, bl[2], bl[3]);
            mma_bf16(acc[2 * p + 1], alo, bh[2], bh[3]);
        }
        {
            u32 bh[2], bl[2];
            ldsm2(bh, sb + SM_BHI + b2_off + koff);
            ldsm2(bl, sb + SM_BLO + b2_off + koff);
            mma_bf16(acc[8], ahi, bh[0], bh[1]);
            mma_bf16(acc[8], ahi, bl[0], bl[1]);
            mma_bf16(acc[8], alo, bh[0], bh[1]);
        }
    }

    float n0 = __shfl_sync(0xffffffffu, acc[8][0], lane & ~3);
    float n1 = __shfl_sync(0xffffffffu, acc[8][2], lane & ~3);
    float dv0 = 1.f / (n0 + EPS);
    float dv1 = 1.f / (n1 + EPS);

    const int r0 = l0 + mbase + (lane >> 2);
    const int col = 2 * (lane & 3);
    size_t g0 = (((size_t)(n * LL + r0)) * HH + h) * DD;
    size_t g1 = g0 + (size_t)8 * HH * DD;

    #pragma unroll
    for (int nt = 0; nt < 8; nt++) {
        *(float2*)&out[g0 + nt * 8 + col] =
            make_float2(acc[nt][0] * dv0, acc[nt][1] * dv0);
        *(float2*)&out[g1 + nt * 8 + col] =
            make_float2(acc[nt][2] * dv1, acc[nt][3] * dv1);
    }
}

extern "C" void kernel_launch(void* const* d_in, const int* in_sizes, int n_in,
                              void* d_out, int out_size)
{
    const float* q   = (const float*)d_in[0];
    const float* k   = (const float*)d_in[1];
    const float* v   = (const float*)d_in[2];
    const float* qm  = (const float*)d_in[3];
    const float* kvm = (const float*)d_in[4];
    float* out = (float*)d_out;

    static bool attr_done = false;
    if (!attr_done) {
        cudaFuncSetAttribute(out_mma_kernel,
                             cudaFuncAttributeMaxDynamicSharedMemorySize,
                             OUT_SMEM_BYTES);
        attr_done = true;
    }

    kv_mma_kernel<<<dim3(NH, CHA), 128>>>(k, v, kvm);
    kv_reduce_kernel<<<(NH * PART_STRIDE) / 256, 256>>>();
    out_mma_kernel<<<dim3(NH, 64), 256, OUT_SMEM_BYTES>>>(q, qm, out);
}